// round 13
// baseline (speedup 1.0000x reference)
#include <cuda_runtime.h>
#include <cuda_bf16.h>
#include <cuda_fp16.h>
#include <cstdint>

#define SEQ 1024
#define BSZ 8
#define EMBED 512
#define NH 8
#define QHD 32
#define PD 4
#define IN_PROJ 544

// Q/K stored as packed hi/lo bf16 rows: 128B per (s) row = [hi bf16 x32 | lo bf16 x32]
__device__ __align__(16) char g_Qhl[BSZ * NH * SEQ * 128];   // 8 MB
__device__ __align__(16) char g_Khl[BSZ * NH * SEQ * 128];   // 8 MB
__device__ float g_P[BSZ * NH * SEQ * PD];                   // 1 MB
__device__ __align__(16) __half g_pos16[SEQ * SEQ * PD];     // 8 MB

// ---------------------------------------------------------------------------
// Kernel 0: pos f32 -> fp16
// ---------------------------------------------------------------------------
__global__ __launch_bounds__(256) void pos_cvt_kernel(const float* __restrict__ pos)
{
    const int idx = blockIdx.x * 256 + threadIdx.x;   // over SEQ*SEQ
    const float4 v = ((const float4*)pos)[idx];
    __half2 a = __floats2half2_rn(v.x, v.y);
    __half2 b = __floats2half2_rn(v.z, v.w);
    uint2 pk;
    pk.x = *(uint32_t*)&a;
    pk.y = *(uint32_t*)&b;
    ((uint2*)g_pos16)[idx] = pk;
}

// ========================= warp-MMA plumbing (sm_80+) =======================
__device__ __forceinline__ uint32_t smem_u32(const void* p) {
    uint32_t a;
    asm("{ .reg .u64 t; cvta.to.shared.u64 t, %1; cvt.u32.u64 %0, t; }"
        : "=r"(a) : "l"(p));
    return a;
}

#define LDSM4(d0, d1, d2, d3, a) \
    asm volatile("ldmatrix.sync.aligned.m8n8.x4.shared.b16 {%0,%1,%2,%3}, [%4];" \
                 : "=r"(d0), "=r"(d1), "=r"(d2), "=r"(d3) : "r"(a))

__device__ __forceinline__ void mma16816(float* d, const uint32_t* a,
                                         uint32_t b0, uint32_t b1) {
    asm volatile(
        "mma.sync.aligned.m16n8k16.row.col.f32.bf16.bf16.f32 "
        "{%0,%1,%2,%3}, {%4,%5,%6,%7}, {%8,%9}, {%0,%1,%2,%3};"
        : "+f"(d[0]), "+f"(d[1]), "+f"(d[2]), "+f"(d[3])
        : "r"(a[0]), "r"(a[1]), "r"(a[2]), "r"(a[3]), "r"(b0), "r"(b1));
}

// split 8 consecutive f32 into hi/lo bf16x2 quads written to two SMEM planes
__device__ __forceinline__ void cvt8s(const float* __restrict__ src,
                                      char* __restrict__ hirow,
                                      char* __restrict__ lorow, int c,
                                      bool valid) {
    float f[8];
    if (valid) {
        float4 v0 = *(const float4*)src;
        float4 v1 = *(const float4*)(src + 4);
        f[0] = v0.x; f[1] = v0.y; f[2] = v0.z; f[3] = v0.w;
        f[4] = v1.x; f[5] = v1.y; f[6] = v1.z; f[7] = v1.w;
    } else {
#pragma unroll
        for (int i = 0; i < 8; i++) f[i] = 0.f;
    }
    uint32_t hp[4], lp[4];
#pragma unroll
    for (int p = 0; p < 4; p++) {
        float a = f[2 * p], bq = f[2 * p + 1];
        __nv_bfloat16 ah = __float2bfloat16(a);
        __nv_bfloat16 bh = __float2bfloat16(bq);
        __nv_bfloat162 hh; hh.x = ah; hh.y = bh;
        __nv_bfloat162 ll;
        ll.x = __float2bfloat16(a - __bfloat162float(ah));
        ll.y = __float2bfloat16(bq - __bfloat162float(bh));
        hp[p] = *(uint32_t*)&hh;
        lp[p] = *(uint32_t*)&ll;
    }
    *(uint4*)(hirow + c * 16) = make_uint4(hp[0], hp[1], hp[2], hp[3]);
    *(uint4*)(lorow + c * 16) = make_uint4(lp[0], lp[1], lp[2], lp[3]);
}

// ---------------------------------------------------------------------------
// Kernel 1: projection on HMMA (unchanged, ~49us).
// ---------------------------------------------------------------------------
#define PPITCH 144
#define XHI_OFF 0
#define XLO_OFF 18432
#define WHI_OFF 36864
#define WLO_OFF 46080
#define PROJ_SMEM 55296
#define OTP 68

__global__ __launch_bounds__(256, 2) void proj_mma_kernel(
    const float* __restrict__ x, const float* __restrict__ W,
    const float* __restrict__ bias)
{
    extern __shared__ __align__(16) char sm[];
    char* Xhi = sm + XHI_OFF;
    char* Xlo = sm + XLO_OFF;
    char* Whi = sm + WHI_OFF;
    char* Wlo = sm + WLO_OFF;
    float* OT = (float*)sm;

    const int tid = threadIdx.x;
    const int w = tid >> 5, lane = tid & 31;
    const int n0 = blockIdx.x * 64;
    const int m0 = blockIdx.y * 128;
    const int wm = w & 3;
    const int wn = w >> 2;

    const uint32_t XhiA = smem_u32(Xhi), XloA = smem_u32(Xlo);
    const uint32_t WhiA = smem_u32(Whi), WloA = smem_u32(Wlo);

    const int r0 = lane >> 2;
    const int scol = 2 * (lane & 3);

    float acc[2][4][4];
#pragma unroll
    for (int mt = 0; mt < 2; mt++)
#pragma unroll
        for (int nt = 0; nt < 4; nt++) {
            const int c = n0 + wn * 32 + nt * 8 + scol;
            const float b0v = (c < IN_PROJ) ? bias[c] : 0.f;
            const float b1v = (c + 1 < IN_PROJ) ? bias[c + 1] : 0.f;
            acc[mt][nt][0] = b0v; acc[mt][nt][1] = b1v;
            acc[mt][nt][2] = b0v; acc[mt][nt][3] = b1v;
        }

    for (int k0 = 0; k0 < EMBED; k0 += 64) {
        __syncthreads();
#pragma unroll
        for (int i = 0; i < 4; i++) {
            const int idx = tid + i * 256;
            const int r = idx >> 3, oct = idx & 7;
            cvt8s(&x[(size_t)(m0 + r) * EMBED + k0 + oct * 8],
                  Xhi + r * PPITCH, Xlo + r * PPITCH, oct, true);
        }
#pragma unroll
        for (int i = 0; i < 2; i++) {
            const int idx = tid + i * 256;
            const int r = idx >> 3, oct = idx & 7;
            cvt8s(&W[(size_t)(n0 + r) * EMBED + k0 + oct * 8],
                  Whi + r * PPITCH, Wlo + r * PPITCH, oct, n0 + r < IN_PROJ);
        }
        __syncthreads();

        const int arow = (lane & 7) + ((lane >> 3) & 1) * 8;
        const int ab = ((lane >> 4) & 1) * 16;
        const int brow = lane & 7, bb = (lane >> 3) * 16;

#pragma unroll
        for (int kh = 0; kh < 2; kh++) {
            uint32_t A[2][2][2][4];
#pragma unroll
            for (int mt = 0; mt < 2; mt++)
#pragma unroll
                for (int kr = 0; kr < 2; kr++) {
                    const uint32_t off =
                        (wm * 32 + mt * 16 + arow) * PPITCH + ab +
                        kh * 64 + kr * 32;
                    LDSM4(A[mt][0][kr][0], A[mt][0][kr][1],
                          A[mt][0][kr][2], A[mt][0][kr][3], XhiA + off);
                    LDSM4(A[mt][1][kr][0], A[mt][1][kr][1],
                          A[mt][1][kr][2], A[mt][1][kr][3], XloA + off);
                }
            uint32_t B[4][2][4];
#pragma unroll
            for (int nt = 0; nt < 4; nt++) {
                const uint32_t off =
                    (wn * 32 + nt * 8 + brow) * PPITCH + bb + kh * 64;
                LDSM4(B[nt][0][0], B[nt][0][1], B[nt][0][2], B[nt][0][3],
                      WhiA + off);
                LDSM4(B[nt][1][0], B[nt][1][1], B[nt][1][2], B[nt][1][3],
                      WloA + off);
            }
#pragma unroll
            for (int kr = 0; kr < 2; kr++)
#pragma unroll
                for (int mt = 0; mt < 2; mt++)
#pragma unroll
                    for (int nt = 0; nt < 4; nt++) {
                        mma16816(acc[mt][nt], A[mt][0][kr],
                                 B[nt][0][kr * 2], B[nt][0][kr * 2 + 1]);
                        mma16816(acc[mt][nt], A[mt][0][kr],
                                 B[nt][1][kr * 2], B[nt][1][kr * 2 + 1]);
                        mma16816(acc[mt][nt], A[mt][1][kr],
                                 B[nt][0][kr * 2], B[nt][0][kr * 2 + 1]);
                    }
        }
    }
    __syncthreads();

#pragma unroll
    for (int mt = 0; mt < 2; mt++)
#pragma unroll
        for (int nt = 0; nt < 4; nt++) {
            const int mr0 = wm * 32 + mt * 16 + r0;
            const int c = wn * 32 + nt * 8 + scol;
            *(float2*)&OT[mr0 * OTP + c] =
                make_float2(acc[mt][nt][0], acc[mt][nt][1]);
            *(float2*)&OT[(mr0 + 8) * OTP + c] =
                make_float2(acc[mt][nt][2], acc[mt][nt][3]);
        }
    __syncthreads();

    const int mr = tid >> 1, half = tid & 1;
    const int m = m0 + mr;
    const int s = m >> 3, bb2 = m & 7;
    const int nb = blockIdx.x;
    const float* src = &OT[mr * OTP + half * 32];

    if (nb < 8) {
        const int qk = nb >> 2;
        const int hh = (nb & 3) * 2 + half;
        char* row = (qk ? g_Khl : g_Qhl) +
                    (((size_t)(bb2 * NH + hh)) * SEQ + s) * 128;
        uint32_t hp[16], lp[16];
#pragma unroll
        for (int p = 0; p < 16; p++) {
            const float a = src[2 * p], bq = src[2 * p + 1];
            __nv_bfloat16 ah = __float2bfloat16(a);
            __nv_bfloat16 bh = __float2bfloat16(bq);
            __nv_bfloat162 hh2; hh2.x = ah; hh2.y = bh;
            __nv_bfloat162 ll;
            ll.x = __float2bfloat16(a - __bfloat162float(ah));
            ll.y = __float2bfloat16(bq - __bfloat162float(bh));
            hp[p] = *(uint32_t*)&hh2;
            lp[p] = *(uint32_t*)&ll;
        }
#pragma unroll
        for (int q = 0; q < 4; q++) {
            *(uint4*)(row + q * 16) =
                make_uint4(hp[4 * q], hp[4 * q + 1], hp[4 * q + 2], hp[4 * q + 3]);
            *(uint4*)(row + 64 + q * 16) =
                make_uint4(lp[4 * q], lp[4 * q + 1], lp[4 * q + 2], lp[4 * q + 3]);
        }
    } else if (half == 0) {
#pragma unroll
        for (int hh = 0; hh < 8; hh++) {
            float4 v = *(const float4*)&src[hh * 4];
            *(float4*)&g_P[(((size_t)(bb2 * NH + hh)) * SEQ + s) * PD] = v;
        }
    }
}

// ---------------------------------------------------------------------------
// Kernel 2: HMMA QK, CTA = (b, 2 heads, 16 t-rows), 512 threads.
// Phase 1: 8 warps per head compute that head's scores into a 32-row tile.
// Phase 2: warp = one t-row for BOTH heads -> pos/off loaded once per 2 rows.
// ---------------------------------------------------------------------------
#define KPITCH 144
#define SCK 256
#define SCP 1032
#define KH_STRIDE (SCK * KPITCH)            // 36864

#define SC_OFF  0                           // 32*1032*4 = 132096
#define K_OFF   132096                      // 2*256*144 = 73728
#define Q_OFF   (132096 + 73728)            // 2*16*144 = 4608
#define PS_OFF  (Q_OFF + 4608)              // 32*16 = 512
#define SM_TOTAL (PS_OFF + 512)             // 210944 B

__global__ __launch_bounds__(512, 1)
void attn_mma_kernel(const float* __restrict__ off, float* __restrict__ out)
{
    extern __shared__ __align__(16) char smraw[];
    float* sc = (float*)(smraw + SC_OFF);    // rows: hq*16 + t-local
    char* Ksm = smraw + K_OFF;
    char* Qsm = smraw + Q_OFF;
    float4* Ps = (float4*)(smraw + PS_OFF);  // [hq*16 + t-local]

    const int tid = threadIdx.x;
    const int w = tid >> 5, lane = tid & 31;
    const int t0g = blockIdx.x * 16;
    const int hbase = blockIdx.y * 2;
    const int b = blockIdx.z;

    const char* Kg = g_Khl + ((size_t)(b * NH + hbase)) * SEQ * 128;

    // stage Q rows (2h x 16 x 128B) + P
    if (tid < 256) {
        const int r = tid >> 3, oct = tid & 7;       // r: hq*16 + tr
        const int hq = r >> 4, tr = r & 15;
        const char* Qg = g_Qhl +
            (((size_t)(b * NH + hbase + hq)) * SEQ + t0g + tr) * 128;
        *(uint4*)(Qsm + r * KPITCH + oct * 16) = *(const uint4*)(Qg + oct * 16);
    }
    if (tid < 32) {
        const int hq = tid >> 4, tr = tid & 15;
        Ps[tid] = *(const float4*)&g_P[
            (((size_t)(b * NH + hbase + hq)) * SEQ + t0g + tr) * PD];
    }
    __syncthreads();

    const uint32_t Qaddr = smem_u32(Qsm);
    const uint32_t Kaddr = smem_u32(Ksm);

    const int hw = w >> 3;        // warp's head (phase 1)
    const int ws = w & 7;         // warp's s-slot within head

    // A fragments for this warp's head: [prec][kstep][4]
    uint32_t aq[2][2][4];
    {
        const int arow = (lane & 7) + ((lane >> 3) & 1) * 8;
        const int ab = ((lane >> 4) & 1) * 16;
#pragma unroll
        for (int prec = 0; prec < 2; prec++)
#pragma unroll
            for (int kk = 0; kk < 2; kk++) {
                const uint32_t ad = Qaddr + (hw * 16 + arow) * KPITCH +
                                    ab + kk * 32 + prec * 64;
                LDSM4(aq[prec][kk][0], aq[prec][kk][1],
                      aq[prec][kk][2], aq[prec][kk][3], ad);
            }
    }

    const int r0 = lane >> 2, r1 = r0 + 8;
    const int scol = 2 * (lane & 3);

    // ---- phase 1: MMA -> raw scores in SMEM tile ---------------------------
#pragma unroll
    for (int ch = 0; ch < 4; ch++) {
        __syncthreads();   // previous chunk's B-frags consumed
        // stage K chunk: 2h x 256 rows x 8 uint4 = 4096 slots over 512 threads
#pragma unroll
        for (int i = 0; i < 8; i++) {
            const int idx = tid + i * 512;
            const int hq = idx >> 11;
            const int r = (idx >> 3) & 255;
            const int oct = idx & 7;
            *(uint4*)(Ksm + hq * KH_STRIDE + r * KPITCH + oct * 16) =
                *(const uint4*)(Kg + ((size_t)hq * SEQ + ch * SCK + r) * 128 +
                                oct * 16);
        }
        __syncthreads();

#pragma unroll
        for (int j = 0; j < 4; j++) {
            const int s0loc = ws * 32 + j * 8;   // 8 warps x 32 = 256 s/head
            uint32_t bh[4], bl[4];
            {
                const uint32_t bad = Kaddr + hw * KH_STRIDE +
                                     (s0loc + (lane & 7)) * KPITCH +
                                     (lane >> 3) * 16;
                LDSM4(bh[0], bh[1], bh[2], bh[3], bad);
                LDSM4(bl[0], bl[1], bl[2], bl[3], bad + 64);
            }
            float ac[4] = {0.f, 0.f, 0.f, 0.f};
            mma16816(ac, aq[0][0], bh[0], bh[1]);
            mma16816(ac, aq[0][1], bh[2], bh[3]);
            mma16816(ac, aq[0][0], bl[0], bl[1]);
            mma16816(ac, aq[0][1], bl[2], bl[3]);
            mma16816(ac, aq[1][0], bh[0], bh[1]);
            mma16816(ac, aq[1][1], bh[2], bh[3]);

            const int col = ch * SCK + s0loc + scol;
            *(float2*)&sc[(hw * 16 + r0) * SCP + col] = make_float2(ac[0], ac[1]);
            *(float2*)&sc[(hw * 16 + r1) * SCP + col] = make_float2(ac[2], ac[3]);
        }
    }
    __syncthreads();

    // ---- phase 2: warp = one t-row, BOTH heads; pos/off loaded once --------
    {
        const int tl = w;                      // 16 warps = 16 t-rows
        const int t = t0g + tl;
        const float4 p40 = Ps[tl];             // head hbase
        const float4 p41 = Ps[16 + tl];        // head hbase+1
        const uint2* posrow = (const uint2*)(g_pos16 + (size_t)t * SEQ * PD);
        const float* offrow = off + ((size_t)b * SEQ + t) * SEQ;
        const float* scrow0 = &sc[tl * SCP];
        const float* scrow1 = &sc[(16 + tl) * SCP];

        float v0[32], v1[32];
        float sum0 = 0.f, sum1 = 0.f;
#pragma unroll
        for (int i = 0; i < 32; i++) {
            const int s = i * 32 + lane;
            const uint2 pp = posrow[s];
            const __half2 h0 = *(const __half2*)&pp.x;
            const __half2 h1 = *(const __half2*)&pp.y;
            const float2 f0 = __half22float2(h0);
            const float2 f1 = __half22float2(h1);
            const float o = offrow[s];
            float a0 = scrow0[s] + o +
                       p40.x * f0.x + p40.y * f0.y + p40.z * f1.x + p40.w * f1.y;
            float a1 = scrow1[s] + o +
                       p41.x * f0.x + p41.y * f0.y + p41.z * f1.x + p41.w * f1.y;
            a0 = __expf(a0);
            a1 = __expf(a1);
            v0[i] = a0; v1[i] = a1;
            sum0 += a0; sum1 += a1;
        }
#pragma unroll
        for (int o_ = 16; o_ > 0; o_ >>= 1) {
            sum0 += __shfl_xor_sync(0xffffffffu, sum0, o_);
            sum1 += __shfl_xor_sync(0xffffffffu, sum1, o_);
        }
        const float inv0 = 1.0f / sum0;
        const float inv1 = 1.0f / sum1;

        float* orow0 = &out[(((size_t)(hbase * BSZ + b)) * SEQ + t) * SEQ];
        float* orow1 = &out[(((size_t)((hbase + 1) * BSZ + b)) * SEQ + t) * SEQ];
#pragma unroll
        for (int i = 0; i < 32; i++) {
            orow0[i * 32 + lane] = v0[i] * inv0;
            orow1[i * 32 + lane] = v1[i] * inv1;
        }
    }
}

// ---------------------------------------------------------------------------
extern "C" void kernel_launch(void* const* d_in, const int* in_sizes, int n_in,
                              void* d_out, int out_size)
{
    const float* x    = (const float*)d_in[0];
    const float* pos  = (const float*)d_in[1];
    const float* off  = (const float*)d_in[2];
    const float* W    = (const float*)d_in[3];
    const float* bias = (const float*)d_in[4];
    float* out = (float*)d_out;

    cudaFuncSetAttribute(proj_mma_kernel,
                         cudaFuncAttributeMaxDynamicSharedMemorySize, PROJ_SMEM);
    cudaFuncSetAttribute(attn_mma_kernel,
                         cudaFuncAttributeMaxDynamicSharedMemorySize, SM_TOTAL);

    pos_cvt_kernel<<<(SEQ * SEQ) / 256, 256>>>(pos);

    dim3 gproj(9, (SEQ * BSZ) / 128);                     // 9 x 64
    proj_mma_kernel<<<gproj, 256, PROJ_SMEM>>>(x, W, bias);

    dim3 gattn(SEQ / 16, NH / 2, BSZ);                    // 64 x 4 x 8
    attn_mma_kernel<<<gattn, 512, SM_TOTAL>>>(off, out);
}

// round 14
// speedup vs baseline: 1.1365x; 1.1365x over previous
#include <cuda_runtime.h>
#include <cuda_bf16.h>
#include <cuda_fp16.h>
#include <cstdint>

#define SEQ 1024
#define BSZ 8
#define EMBED 512
#define NH 8
#define QHD 32
#define PD 4
#define IN_PROJ 544

// Q/K stored as packed hi/lo bf16 rows: 128B per (s) row = [hi bf16 x32 | lo bf16 x32]
__device__ __align__(16) char g_Qhl[BSZ * NH * SEQ * 128];   // 8 MB
__device__ __align__(16) char g_Khl[BSZ * NH * SEQ * 128];   // 8 MB
__device__ float g_P[BSZ * NH * SEQ * PD];                   // 1 MB
__device__ __align__(16) __half g_pos16[SEQ * SEQ * PD];     // 8 MB

// ---------------------------------------------------------------------------
// Kernel 0: pos f32 -> fp16
// ---------------------------------------------------------------------------
__global__ __launch_bounds__(256) void pos_cvt_kernel(const float* __restrict__ pos)
{
    const int idx = blockIdx.x * 256 + threadIdx.x;   // over SEQ*SEQ
    const float4 v = ((const float4*)pos)[idx];
    __half2 a = __floats2half2_rn(v.x, v.y);
    __half2 b = __floats2half2_rn(v.z, v.w);
    uint2 pk;
    pk.x = *(uint32_t*)&a;
    pk.y = *(uint32_t*)&b;
    ((uint2*)g_pos16)[idx] = pk;
}

// ========================= warp-MMA plumbing (sm_80+) =======================
__device__ __forceinline__ uint32_t smem_u32(const void* p) {
    uint32_t a;
    asm("{ .reg .u64 t; cvta.to.shared.u64 t, %1; cvt.u32.u64 %0, t; }"
        : "=r"(a) : "l"(p));
    return a;
}

#define LDSM4(d0, d1, d2, d3, a) \
    asm volatile("ldmatrix.sync.aligned.m8n8.x4.shared.b16 {%0,%1,%2,%3}, [%4];" \
                 : "=r"(d0), "=r"(d1), "=r"(d2), "=r"(d3) : "r"(a))

#define CP_ASYNC16(dst, src) \
    asm volatile("cp.async.cg.shared.global [%0], [%1], 16;" \
                 :: "r"(dst), "l"(src) : "memory")
#define CP_COMMIT() asm volatile("cp.async.commit_group;" ::: "memory")
#define CP_WAIT(N)  asm volatile("cp.async.wait_group %0;" :: "n"(N) : "memory")

__device__ __forceinline__ void mma16816(float* d, const uint32_t* a,
                                         uint32_t b0, uint32_t b1) {
    asm volatile(
        "mma.sync.aligned.m16n8k16.row.col.f32.bf16.bf16.f32 "
        "{%0,%1,%2,%3}, {%4,%5,%6,%7}, {%8,%9}, {%0,%1,%2,%3};"
        : "+f"(d[0]), "+f"(d[1]), "+f"(d[2]), "+f"(d[3])
        : "r"(a[0]), "r"(a[1]), "r"(a[2]), "r"(a[3]), "r"(b0), "r"(b1));
}

// split 8 consecutive f32 into hi/lo bf16x2 quads written to two SMEM planes
__device__ __forceinline__ void cvt8s(const float* __restrict__ src,
                                      char* __restrict__ hirow,
                                      char* __restrict__ lorow, int c,
                                      bool valid) {
    float f[8];
    if (valid) {
        float4 v0 = *(const float4*)src;
        float4 v1 = *(const float4*)(src + 4);
        f[0] = v0.x; f[1] = v0.y; f[2] = v0.z; f[3] = v0.w;
        f[4] = v1.x; f[5] = v1.y; f[6] = v1.z; f[7] = v1.w;
    } else {
#pragma unroll
        for (int i = 0; i < 8; i++) f[i] = 0.f;
    }
    uint32_t hp[4], lp[4];
#pragma unroll
    for (int p = 0; p < 4; p++) {
        float a = f[2 * p], bq = f[2 * p + 1];
        __nv_bfloat16 ah = __float2bfloat16(a);
        __nv_bfloat16 bh = __float2bfloat16(bq);
        __nv_bfloat162 hh; hh.x = ah; hh.y = bh;
        __nv_bfloat162 ll;
        ll.x = __float2bfloat16(a - __bfloat162float(ah));
        ll.y = __float2bfloat16(bq - __bfloat162float(bh));
        hp[p] = *(uint32_t*)&hh;
        lp[p] = *(uint32_t*)&ll;
    }
    *(uint4*)(hirow + c * 16) = make_uint4(hp[0], hp[1], hp[2], hp[3]);
    *(uint4*)(lorow + c * 16) = make_uint4(lp[0], lp[1], lp[2], lp[3]);
}

// ---------------------------------------------------------------------------
// Kernel 1: projection on HMMA (unchanged, ~49us).
// ---------------------------------------------------------------------------
#define PPITCH 144
#define XHI_OFF 0
#define XLO_OFF 18432
#define WHI_OFF 36864
#define WLO_OFF 46080
#define PROJ_SMEM 55296
#define OTP 68

__global__ __launch_bounds__(256, 2) void proj_mma_kernel(
    const float* __restrict__ x, const float* __restrict__ W,
    const float* __restrict__ bias)
{
    extern __shared__ __align__(16) char sm[];
    char* Xhi = sm + XHI_OFF;
    char* Xlo = sm + XLO_OFF;
    char* Whi = sm + WHI_OFF;
    char* Wlo = sm + WLO_OFF;
    float* OT = (float*)sm;

    const int tid = threadIdx.x;
    const int w = tid >> 5, lane = tid & 31;
    const int n0 = blockIdx.x * 64;
    const int m0 = blockIdx.y * 128;
    const int wm = w & 3;
    const int wn = w >> 2;

    const uint32_t XhiA = smem_u32(Xhi), XloA = smem_u32(Xlo);
    const uint32_t WhiA = smem_u32(Whi), WloA = smem_u32(Wlo);

    const int r0 = lane >> 2;
    const int scol = 2 * (lane & 3);

    float acc[2][4][4];
#pragma unroll
    for (int mt = 0; mt < 2; mt++)
#pragma unroll
        for (int nt = 0; nt < 4; nt++) {
            const int c = n0 + wn * 32 + nt * 8 + scol;
            const float b0v = (c < IN_PROJ) ? bias[c] : 0.f;
            const float b1v = (c + 1 < IN_PROJ) ? bias[c + 1] : 0.f;
            acc[mt][nt][0] = b0v; acc[mt][nt][1] = b1v;
            acc[mt][nt][2] = b0v; acc[mt][nt][3] = b1v;
        }

    for (int k0 = 0; k0 < EMBED; k0 += 64) {
        __syncthreads();
#pragma unroll
        for (int i = 0; i < 4; i++) {
            const int idx = tid + i * 256;
            const int r = idx >> 3, oct = idx & 7;
            cvt8s(&x[(size_t)(m0 + r) * EMBED + k0 + oct * 8],
                  Xhi + r * PPITCH, Xlo + r * PPITCH, oct, true);
        }
#pragma unroll
        for (int i = 0; i < 2; i++) {
            const int idx = tid + i * 256;
            const int r = idx >> 3, oct = idx & 7;
            cvt8s(&W[(size_t)(n0 + r) * EMBED + k0 + oct * 8],
                  Whi + r * PPITCH, Wlo + r * PPITCH, oct, n0 + r < IN_PROJ);
        }
        __syncthreads();

        const int arow = (lane & 7) + ((lane >> 3) & 1) * 8;
        const int ab = ((lane >> 4) & 1) * 16;
        const int brow = lane & 7, bb = (lane >> 3) * 16;

#pragma unroll
        for (int kh = 0; kh < 2; kh++) {
            uint32_t A[2][2][2][4];
#pragma unroll
            for (int mt = 0; mt < 2; mt++)
#pragma unroll
                for (int kr = 0; kr < 2; kr++) {
                    const uint32_t off =
                        (wm * 32 + mt * 16 + arow) * PPITCH + ab +
                        kh * 64 + kr * 32;
                    LDSM4(A[mt][0][kr][0], A[mt][0][kr][1],
                          A[mt][0][kr][2], A[mt][0][kr][3], XhiA + off);
                    LDSM4(A[mt][1][kr][0], A[mt][1][kr][1],
                          A[mt][1][kr][2], A[mt][1][kr][3], XloA + off);
                }
            uint32_t B[4][2][4];
#pragma unroll
            for (int nt = 0; nt < 4; nt++) {
                const uint32_t off =
                    (wn * 32 + nt * 8 + brow) * PPITCH + bb + kh * 64;
                LDSM4(B[nt][0][0], B[nt][0][1], B[nt][0][2], B[nt][0][3],
                      WhiA + off);
                LDSM4(B[nt][1][0], B[nt][1][1], B[nt][1][2], B[nt][1][3],
                      WloA + off);
            }
#pragma unroll
            for (int kr = 0; kr < 2; kr++)
#pragma unroll
                for (int mt = 0; mt < 2; mt++)
#pragma unroll
                    for (int nt = 0; nt < 4; nt++) {
                        mma16816(acc[mt][nt], A[mt][0][kr],
                                 B[nt][0][kr * 2], B[nt][0][kr * 2 + 1]);
                        mma16816(acc[mt][nt], A[mt][0][kr],
                                 B[nt][1][kr * 2], B[nt][1][kr * 2 + 1]);
                        mma16816(acc[mt][nt], A[mt][1][kr],
                                 B[nt][0][kr * 2], B[nt][0][kr * 2 + 1]);
                    }
        }
    }
    __syncthreads();

#pragma unroll
    for (int mt = 0; mt < 2; mt++)
#pragma unroll
        for (int nt = 0; nt < 4; nt++) {
            const int mr0 = wm * 32 + mt * 16 + r0;
            const int c = wn * 32 + nt * 8 + scol;
            *(float2*)&OT[mr0 * OTP + c] =
                make_float2(acc[mt][nt][0], acc[mt][nt][1]);
            *(float2*)&OT[(mr0 + 8) * OTP + c] =
                make_float2(acc[mt][nt][2], acc[mt][nt][3]);
        }
    __syncthreads();

    const int mr = tid >> 1, half = tid & 1;
    const int m = m0 + mr;
    const int s = m >> 3, bb2 = m & 7;
    const int nb = blockIdx.x;
    const float* src = &OT[mr * OTP + half * 32];

    if (nb < 8) {
        const int qk = nb >> 2;
        const int hh = (nb & 3) * 2 + half;
        char* row = (qk ? g_Khl : g_Qhl) +
                    (((size_t)(bb2 * NH + hh)) * SEQ + s) * 128;
        uint32_t hp[16], lp[16];
#pragma unroll
        for (int p = 0; p < 16; p++) {
            const float a = src[2 * p], bq = src[2 * p + 1];
            __nv_bfloat16 ah = __float2bfloat16(a);
            __nv_bfloat16 bh = __float2bfloat16(bq);
            __nv_bfloat162 hh2; hh2.x = ah; hh2.y = bh;
            __nv_bfloat162 ll;
            ll.x = __float2bfloat16(a - __bfloat162float(ah));
            ll.y = __float2bfloat16(bq - __bfloat162float(bh));
            hp[p] = *(uint32_t*)&hh2;
            lp[p] = *(uint32_t*)&ll;
        }
#pragma unroll
        for (int q = 0; q < 4; q++) {
            *(uint4*)(row + q * 16) =
                make_uint4(hp[4 * q], hp[4 * q + 1], hp[4 * q + 2], hp[4 * q + 3]);
            *(uint4*)(row + 64 + q * 16) =
                make_uint4(lp[4 * q], lp[4 * q + 1], lp[4 * q + 2], lp[4 * q + 3]);
        }
    } else if (half == 0) {
#pragma unroll
        for (int hh = 0; hh < 8; hh++) {
            float4 v = *(const float4*)&src[hh * 4];
            *(float4*)&g_P[(((size_t)(bb2 * NH + hh)) * SEQ + s) * PD] = v;
        }
    }
}

// ---------------------------------------------------------------------------
// Kernel 2: HMMA QK, TT=32, 512 threads. Score tile 32x1024 in SMEM.
// K staged via cp.async double buffer (2 x 256 rows), 4 chunks pipelined.
// Phase 2: warp = t-row, fp16 pos, register exp (round-12 proven form).
// ---------------------------------------------------------------------------
#define KPITCH 144
#define SCK 256
#define NCHK 4
#define KBUF (SCK * KPITCH)                 // 36864
#define SCP 1032

#define SC_OFF  0                           // 32*1032*4 = 132096
#define K_OFF   132096                      // 2*36864 = 73728
#define Q_OFF   (132096 + 73728)            // 32*144 = 4608
#define PS_OFF  (Q_OFF + 4608)              // 32*16 = 512
#define SM_TOTAL (PS_OFF + 512)             // 210944 B

__global__ __launch_bounds__(512, 1)
void attn_mma_kernel(const float* __restrict__ off, float* __restrict__ out)
{
    extern __shared__ __align__(16) char smraw[];
    float* sc = (float*)(smraw + SC_OFF);
    char* Ksm = smraw + K_OFF;
    char* Qsm = smraw + Q_OFF;
    float4* Ps = (float4*)(smraw + PS_OFF);

    const int tid = threadIdx.x;
    const int w = tid >> 5, lane = tid & 31;
    const int t0g = blockIdx.x * 32;
    const int h = blockIdx.y, b = blockIdx.z;

    const char* Qg = g_Qhl + (((size_t)(b * NH + h)) * SEQ + t0g) * 128;
    const char* Kg = g_Khl + ((size_t)(b * NH + h)) * SEQ * 128;
    const float* Pg = g_P + ((size_t)(b * NH + h)) * SEQ * PD;

    const uint32_t Qaddr = smem_u32(Qsm);
    const uint32_t Kaddr = smem_u32(Ksm);

    // K staging via cp.async: 256 rows x 8 uint4 = 2048 slots / 512 thr = 4 ea
    const int kr_ = tid >> 3, koct = tid & 7;   // row/oct base for this thread
    // prologue: chunks 0 and 1
#pragma unroll
    for (int pc = 0; pc < 2; pc++) {
#pragma unroll
        for (int i = 0; i < 4; i++) {
            const int r = kr_ + i * 64;
            CP_ASYNC16(Kaddr + pc * KBUF + r * KPITCH + koct * 16,
                       Kg + (size_t)(pc * SCK + r) * 128 + koct * 16);
        }
        CP_COMMIT();
    }

    // stage Q rows (32 x 128B) + P (regular loads, overlap with cp.async)
    if (tid < 256) {
        const int r = tid >> 3, oct = tid & 7;
        *(uint4*)(Qsm + r * KPITCH + oct * 16) =
            *(const uint4*)(Qg + (size_t)r * 128 + oct * 16);
    }
    if (tid < 32)
        Ps[tid] = *(const float4*)&Pg[(size_t)(t0g + tid) * PD];
    __syncthreads();

    // A fragments: [mt][prec][kstep][4] for the two m16 tiles
    uint32_t aq[2][2][2][4];
    {
        const int arow = (lane & 7) + ((lane >> 3) & 1) * 8;
        const int ab = ((lane >> 4) & 1) * 16;
#pragma unroll
        for (int mt = 0; mt < 2; mt++)
#pragma unroll
            for (int prec = 0; prec < 2; prec++)
#pragma unroll
                for (int kk = 0; kk < 2; kk++) {
                    const uint32_t ad = Qaddr + (mt * 16 + arow) * KPITCH +
                                        ab + kk * 32 + prec * 64;
                    LDSM4(aq[mt][prec][kk][0], aq[mt][prec][kk][1],
                          aq[mt][prec][kk][2], aq[mt][prec][kk][3], ad);
                }
    }

    const int r0 = lane >> 2, r1 = r0 + 8;
    const int scol = 2 * (lane & 3);

    // ---- phase 1: pipelined MMA over 4 chunks ------------------------------
#pragma unroll
    for (int ch = 0; ch < NCHK; ch++) {
        if (ch < NCHK - 1) { CP_WAIT(1); } else { CP_WAIT(0); }
        __syncthreads();
        const uint32_t Kb = Kaddr + (ch & 1) * KBUF;

#pragma unroll
        for (int j = 0; j < 2; j++) {
            const int s0loc = w * 16 + j * 8;   // 16 warps x 16 = 256 s
            uint32_t bh[4], bl[4];
            {
                const uint32_t bad = Kb + (s0loc + (lane & 7)) * KPITCH +
                                     (lane >> 3) * 16;
                LDSM4(bh[0], bh[1], bh[2], bh[3], bad);
                LDSM4(bl[0], bl[1], bl[2], bl[3], bad + 64);
            }
            const int col = ch * SCK + s0loc + scol;
#pragma unroll
            for (int mt = 0; mt < 2; mt++) {
                float ac[4] = {0.f, 0.f, 0.f, 0.f};
                mma16816(ac, aq[mt][0][0], bh[0], bh[1]);
                mma16816(ac, aq[mt][0][1], bh[2], bh[3]);
                mma16816(ac, aq[mt][0][0], bl[0], bl[1]);
                mma16816(ac, aq[mt][0][1], bl[2], bl[3]);
                mma16816(ac, aq[mt][1][0], bh[0], bh[1]);
                mma16816(ac, aq[mt][1][1], bh[2], bh[3]);

                *(float2*)&sc[(mt * 16 + r0) * SCP + col] =
                    make_float2(ac[0], ac[1]);
                *(float2*)&sc[(mt * 16 + r1) * SCP + col] =
                    make_float2(ac[2], ac[3]);
            }
        }
        __syncthreads();   // all warps done reading buffer (ch&1)

        if (ch + 2 < NCHK) {
#pragma unroll
            for (int i = 0; i < 4; i++) {
                const int r = kr_ + i * 64;
                CP_ASYNC16(Kaddr + (ch & 1) * KBUF + r * KPITCH + koct * 16,
                           Kg + (size_t)((ch + 2) * SCK + r) * 128 + koct * 16);
            }
            CP_COMMIT();
        }
    }
    __syncthreads();

    // ---- phase 2: single-pass epilogue (warp = t-row, exp in registers) ----
#pragma unroll
    for (int rr = 0; rr < 2; rr++) {
        const int tl = w * 2 + rr;
        const int t = t0g + tl;
        const float4 p4 = Ps[tl];
        const uint2* posrow = (const uint2*)(g_pos16 + (size_t)t * SEQ * PD);
        const float* offrow = off + ((size_t)b * SEQ + t) * SEQ;
        const float* scrow = &sc[tl * SCP];

        float v[32];
        float sum = 0.f;
#pragma unroll
        for (int i = 0; i < 32; i++) {
            const int s = i * 32 + lane;
            const uint2 pp = posrow[s];                 // 8B fp16 pos[4]
            const __half2 h0 = *(const __half2*)&pp.x;
            const __half2 h1 = *(const __half2*)&pp.y;
            const float2 f0 = __half22float2(h0);
            const float2 f1 = __half22float2(h1);
            float val = scrow[s] + offrow[s] +
                        p4.x * f0.x + p4.y * f0.y + p4.z * f1.x + p4.w * f1.y;
            val = __expf(val);
            v[i] = val;
            sum += val;
        }
#pragma unroll
        for (int o_ = 16; o_ > 0; o_ >>= 1)
            sum += __shfl_xor_sync(0xffffffffu, sum, o_);
        const float inv = 1.0f / sum;

        float* orow = &out[(((size_t)(h * BSZ + b)) * SEQ + t) * SEQ];
#pragma unroll
        for (int i = 0; i < 32; i++)
            orow[i * 32 + lane] = v[i] * inv;
    }
}

// ---------------------------------------------------------------------------
extern "C" void kernel_launch(void* const* d_in, const int* in_sizes, int n_in,
                              void* d_out, int out_size)
{
    const float* x    = (const float*)d_in[0];
    const float* pos  = (const float*)d_in[1];
    const float* off  = (const float*)d_in[2];
    const float* W    = (const float*)d_in[3];
    const float* bias = (const float*)d_in[4];
    float* out = (float*)d_out;

    cudaFuncSetAttribute(proj_mma_kernel,
                         cudaFuncAttributeMaxDynamicSharedMemorySize, PROJ_SMEM);
    cudaFuncSetAttribute(attn_mma_kernel,
                         cudaFuncAttributeMaxDynamicSharedMemorySize, SM_TOTAL);

    pos_cvt_kernel<<<(SEQ * SEQ) / 256, 256>>>(pos);

    dim3 gproj(9, (SEQ * BSZ) / 128);                     // 9 x 64
    proj_mma_kernel<<<gproj, 256, PROJ_SMEM>>>(x, W, bias);

    dim3 gattn(SEQ / 32, NH, BSZ);                        // 32 x 8 x 8
    attn_mma_kernel<<<gattn, 512, SM_TOTAL>>>(off, out);
}